// round 4
// baseline (speedup 1.0000x reference)
#include <cuda_runtime.h>
#include <cuda_bf16.h>

#define FULL_MASK 0xffffffffu

__global__ __launch_bounds__(256, 2) void anfis_kernel(
    const float* __restrict__ x,
    const float* __restrict__ mu,
    const float* __restrict__ sg,
    const float* __restrict__ ta,
    const float* __restrict__ tb,
    const float* __restrict__ tc,
    const float* __restrict__ td,
    const float* __restrict__ mfmix,
    const float* __restrict__ tnw,
    const float* __restrict__ conseq,
    const int*   __restrict__ ridx,
    float* __restrict__ out0,   // [B]
    float* __restrict__ outN,   // [B,128]
    float* __restrict__ outM,   // [B,14]
    int B)
{
    const int tid    = blockIdx.x * blockDim.x + threadIdx.x;
    const int warp   = tid >> 5;
    const int lane   = tid & 31;
    const int nwarps = (gridDim.x * blockDim.x) >> 5;

    // ---- per-lane rules: r = lane + 32*k (k=0..3), shared by both elements ----
    float cq[4][8];
    int   mask[4];
#pragma unroll
    for (int k = 0; k < 4; ++k) {
        const int r = lane + 32 * k;
        const float4* cp = reinterpret_cast<const float4*>(conseq + r * 8);
        float4 c0 = cp[0], c1 = cp[1];
        cq[k][0] = c0.x; cq[k][1] = c0.y; cq[k][2] = c0.z; cq[k][3] = c0.w;
        cq[k][4] = c1.x; cq[k][5] = c1.y; cq[k][6] = c1.z; cq[k][7] = c1.w;
        int m = 0;
#pragma unroll
        for (int f = 0; f < 7; ++f) m |= (ridx[r * 7 + f] & 1) << f;
        mask[k] = m;
    }

    // Structure check: the 4 masks of a lane must agree on features 2..6.
    const int diff = (mask[0]^mask[1]) | (mask[0]^mask[2]) | (mask[0]^mask[3]);
    const bool fast = __all_sync(FULL_MASK, (diff & 0x7C) == 0);

    // Shuffle source lanes (element 0; element 1 adds +14)
    const int src2 = 4  + ((mask[0] >> 2) & 1);
    const int src3 = 6  + ((mask[0] >> 3) & 1);
    const int src4 = 8  + ((mask[0] >> 4) & 1);
    const int src5 = 10 + ((mask[0] >> 5) & 1);
    const int src6 = 12 + ((mask[0] >> 6) & 1);

    const float alpha = 1.f / (1.f + __expf(-mfmix[0]));
    const float w     = 1.f / (1.f + __expf(-tnw[0]));

    // ---- membership params: lanes 0..27 handle (element = lane/14, j = lane%14) ----
    const int j = (lane < 14) ? lane : (lane < 28 ? lane - 14 : 0);
    float muv = 0.f, i2s = 0.f, av = 0.f, bv = 0.f, cv = 0.f, dv = 0.f;
    float iba = 0.f, idc = 0.f;
    {
        muv = mu[j];
        float s = fmaxf(sg[j], 1e-6f);
        i2s = 1.f / (2.f * s * s);
        float p0 = ta[j], p1 = tb[j], p2 = tc[j], p3 = td[j];
        float t;
        t = fminf(p0, p1); p1 = fmaxf(p0, p1); p0 = t;
        t = fminf(p2, p3); p3 = fmaxf(p2, p3); p2 = t;
        t = fminf(p0, p2); p2 = fmaxf(p0, p2); p0 = t;
        t = fminf(p1, p3); p3 = fmaxf(p1, p3); p1 = t;
        t = fminf(p1, p2); p2 = fmaxf(p1, p2); p1 = t;
        av = p0; bv = p1; cv = p2; dv = p3;
        iba = 1.f / (p1 - p0 + 1e-6f);
        idc = 1.f / (p3 - p2 + 1e-6f);
    }

    if (fast) {
        for (int b0 = 2 * warp; b0 < B; b0 += 2 * nwarps) {
            const bool dual  = (b0 + 1 < B);
            const int active = dual ? 28 : 14;
            const float* xb  = x + (long)b0 * 7;

            // ---- membership for up to 2 elements across lanes 0..27 ----
            float xf = 0.f, memv = 0.f;
            if (lane < active) {
                xf = __ldg(xb + (lane >> 1));   // lane>>1 = 7e + f
                float t     = xf - muv;
                float gauss = __expf(-t * t * i2s);
                float left  = fminf(fmaxf((xf - av) * iba, 0.f), 1.f);
                float right = fminf(fmaxf((dv - xf) * idc, 0.f), 1.f);
                float flat  = (xf >= bv && xf <= cv) ? 1.f : 0.f;
                float trap  = fmaxf(fminf(left, right), flat);
                memv = trap + alpha * (gauss - trap);
                outM[(long)b0 * 14 + lane] = memv;
            }

            // ---- element 0 gathers ----
            float a_g2 = __shfl_sync(FULL_MASK, memv, src2);
            float a_g3 = __shfl_sync(FULL_MASK, memv, src3);
            float a_g4 = __shfl_sync(FULL_MASK, memv, src4);
            float a_g5 = __shfl_sync(FULL_MASK, memv, src5);
            float a_g6 = __shfl_sync(FULL_MASK, memv, src6);
            float a_A0 = __shfl_sync(FULL_MASK, memv, 0);
            float a_B0 = __shfl_sync(FULL_MASK, memv, 1);
            float a_A1 = __shfl_sync(FULL_MASK, memv, 2);
            float a_B1 = __shfl_sync(FULL_MASK, memv, 3);
            // ---- element 1 gathers ----
            float b_g2 = __shfl_sync(FULL_MASK, memv, src2 + 14);
            float b_g3 = __shfl_sync(FULL_MASK, memv, src3 + 14);
            float b_g4 = __shfl_sync(FULL_MASK, memv, src4 + 14);
            float b_g5 = __shfl_sync(FULL_MASK, memv, src5 + 14);
            float b_g6 = __shfl_sync(FULL_MASK, memv, src6 + 14);
            float b_A0 = __shfl_sync(FULL_MASK, memv, 14);
            float b_B0 = __shfl_sync(FULL_MASK, memv, 15);
            float b_A1 = __shfl_sync(FULL_MASK, memv, 16);
            float b_B1 = __shfl_sync(FULL_MASK, memv, 17);

            // ---- x broadcasts for consequent (from the same xf registers) ----
            float ax0 = __shfl_sync(FULL_MASK, xf, 0);
            float ax1 = __shfl_sync(FULL_MASK, xf, 2);
            float ax2 = __shfl_sync(FULL_MASK, xf, 4);
            float ax3 = __shfl_sync(FULL_MASK, xf, 6);
            float ax4 = __shfl_sync(FULL_MASK, xf, 8);
            float ax5 = __shfl_sync(FULL_MASK, xf, 10);
            float ax6 = __shfl_sync(FULL_MASK, xf, 12);
            float bx0 = __shfl_sync(FULL_MASK, xf, 14);
            float bx1 = __shfl_sync(FULL_MASK, xf, 16);
            float bx2 = __shfl_sync(FULL_MASK, xf, 18);
            float bx3 = __shfl_sync(FULL_MASK, xf, 20);
            float bx4 = __shfl_sync(FULL_MASK, xf, 22);
            float bx5 = __shfl_sync(FULL_MASK, xf, 24);
            float bx6 = __shfl_sync(FULL_MASK, xf, 26);

            float a_pp = ((a_g2 * a_g3) * (a_g4 * a_g5)) * a_g6;
            float a_pm = fminf(fminf(fminf(a_g2, a_g3), fminf(a_g4, a_g5)), a_g6);
            float b_pp = ((b_g2 * b_g3) * (b_g4 * b_g5)) * b_g6;
            float b_pm = fminf(fminf(fminf(b_g2, b_g3), fminf(b_g4, b_g5)), b_g6);

            float firA[4], firB[4];
            float s1a = 0.f, s2a = 0.f, s1b = 0.f, s2b = 0.f;
#pragma unroll
            for (int k = 0; k < 4; ++k) {
                const int m = mask[k];
                // element 0
                float u = (m & 1) ? a_B0 : a_A0;
                float v = (m & 2) ? a_B1 : a_A1;
                float p  = a_pp * (u * v);
                float mn = fminf(a_pm, fminf(u, v));
                float fA = mn + w * (p - mn);
                firA[k] = fA;
                // element 1
                float u2 = (m & 1) ? b_B0 : b_A0;
                float v2 = (m & 2) ? b_B1 : b_A1;
                float p2  = b_pp * (u2 * v2);
                float mn2 = fminf(b_pm, fminf(u2, v2));
                float fB = mn2 + w * (p2 - mn2);
                firB[k] = fB;

                float roA = cq[k][0];
                roA = fmaf(cq[k][1], ax0, roA);
                roA = fmaf(cq[k][2], ax1, roA);
                roA = fmaf(cq[k][3], ax2, roA);
                roA = fmaf(cq[k][4], ax3, roA);
                roA = fmaf(cq[k][5], ax4, roA);
                roA = fmaf(cq[k][6], ax5, roA);
                roA = fmaf(cq[k][7], ax6, roA);
                float roB = cq[k][0];
                roB = fmaf(cq[k][1], bx0, roB);
                roB = fmaf(cq[k][2], bx1, roB);
                roB = fmaf(cq[k][3], bx2, roB);
                roB = fmaf(cq[k][4], bx3, roB);
                roB = fmaf(cq[k][5], bx4, roB);
                roB = fmaf(cq[k][6], bx5, roB);
                roB = fmaf(cq[k][7], bx6, roB);

                s1a += fA; s2a = fmaf(fA, roA, s2a);
                s1b += fB; s2b = fmaf(fB, roB, s2b);
            }

            // ---- 4 interleaved butterfly reductions ----
#pragma unroll
            for (int off = 16; off > 0; off >>= 1) {
                s1a += __shfl_xor_sync(FULL_MASK, s1a, off);
                s2a += __shfl_xor_sync(FULL_MASK, s2a, off);
                s1b += __shfl_xor_sync(FULL_MASK, s1b, off);
                s2b += __shfl_xor_sync(FULL_MASK, s2b, off);
            }
            const float invA = __fdividef(1.f, s1a + 1e-8f);
            const float invB = __fdividef(1.f, s1b + 1e-8f);

            float* nbA = outN + (long)b0 * 128 + lane;
            nbA[0]  = firA[0] * invA;
            nbA[32] = firA[1] * invA;
            nbA[64] = firA[2] * invA;
            nbA[96] = firA[3] * invA;
            if (dual) {
                float* nbB = nbA + 128;
                nbB[0]  = firB[0] * invB;
                nbB[32] = firB[1] * invB;
                nbB[64] = firB[2] * invB;
                nbB[96] = firB[3] * invB;
            }
            if (lane == 0) {
                out0[b0] = s2a * invA;
                if (dual) out0[b0 + 1] = s2b * invB;
            }
        }
    } else {
        // ---- generic fallback (structure assumption violated): 1 element/iter ----
        for (int b = warp; b < B; b += nwarps) {
            const float* xb = x + (long)b * 7;
            float xv0 = __ldg(xb+0), xv1 = __ldg(xb+1), xv2 = __ldg(xb+2),
                  xv3 = __ldg(xb+3), xv4 = __ldg(xb+4), xv5 = __ldg(xb+5),
                  xv6 = __ldg(xb+6);
            float memv = 0.f;
            if (lane < 14) {
                float xfv = __ldg(xb + (lane >> 1));
                float t     = xfv - muv;
                float gauss = __expf(-t * t * i2s);
                float left  = fminf(fmaxf((xfv - av) * iba, 0.f), 1.f);
                float right = fminf(fmaxf((dv - xfv) * idc, 0.f), 1.f);
                float flat  = (xfv >= bv && xfv <= cv) ? 1.f : 0.f;
                float trap  = fmaxf(fminf(left, right), flat);
                memv = trap + alpha * (gauss - trap);
                outM[(long)b * 14 + lane] = memv;
            }
            float mA[7], mB[7];
#pragma unroll
            for (int f = 0; f < 7; ++f) {
                mA[f] = __shfl_sync(FULL_MASK, memv, 2 * f);
                mB[f] = __shfl_sync(FULL_MASK, memv, 2 * f + 1);
            }
            float fir[4], s1 = 0.f, s2 = 0.f;
#pragma unroll
            for (int k = 0; k < 4; ++k) {
                const int m = mask[k];
                float p = 1.f, mn = 2.f;
#pragma unroll
                for (int f = 0; f < 7; ++f) {
                    float g = (m & (1 << f)) ? mB[f] : mA[f];
                    p *= g; mn = fminf(mn, g);
                }
                float fk = mn + w * (p - mn);
                fir[k] = fk;
                float ro = cq[k][0];
                ro = fmaf(cq[k][1], xv0, ro);
                ro = fmaf(cq[k][2], xv1, ro);
                ro = fmaf(cq[k][3], xv2, ro);
                ro = fmaf(cq[k][4], xv3, ro);
                ro = fmaf(cq[k][5], xv4, ro);
                ro = fmaf(cq[k][6], xv5, ro);
                ro = fmaf(cq[k][7], xv6, ro);
                s1 += fk;
                s2 = fmaf(fk, ro, s2);
            }
#pragma unroll
            for (int off = 16; off > 0; off >>= 1) {
                s1 += __shfl_xor_sync(FULL_MASK, s1, off);
                s2 += __shfl_xor_sync(FULL_MASK, s2, off);
            }
            const float inv = __fdividef(1.f, s1 + 1e-8f);
            float* nb = outN + (long)b * 128 + lane;
            nb[0]  = fir[0] * inv;
            nb[32] = fir[1] * inv;
            nb[64] = fir[2] * inv;
            nb[96] = fir[3] * inv;
            if (lane == 0) out0[b] = s2 * inv;
        }
    }
}

extern "C" void kernel_launch(void* const* d_in, const int* in_sizes, int n_in,
                              void* d_out, int out_size) {
    const float* x      = (const float*)d_in[0];
    const float* mu     = (const float*)d_in[1];
    const float* sg     = (const float*)d_in[2];
    const float* ta     = (const float*)d_in[3];
    const float* tb     = (const float*)d_in[4];
    const float* tc     = (const float*)d_in[5];
    const float* td     = (const float*)d_in[6];
    const float* mfmix  = (const float*)d_in[7];
    const float* tnw    = (const float*)d_in[8];
    const float* conseq = (const float*)d_in[9];
    const int*   ridx   = (const int*)d_in[10];

    const int B = in_sizes[0] / 7;

    float* o  = (float*)d_out;
    float* oN = o + B;                  // norm_firing [B,128]
    float* oM = o + B + (long)B * 128;  // mem [B,14]

    anfis_kernel<<<1024, 256>>>(x, mu, sg, ta, tb, tc, td, mfmix, tnw,
                                conseq, ridx, o, oN, oM, B);
}

// round 6
// speedup vs baseline: 1.6140x; 1.6140x over previous
#include <cuda_runtime.h>
#include <cuda_bf16.h>

#define FULL_MASK 0xffffffffu

__global__ __launch_bounds__(128, 5) void anfis_kernel(
    const float* __restrict__ x,
    const float* __restrict__ mu,
    const float* __restrict__ sg,
    const float* __restrict__ ta,
    const float* __restrict__ tb,
    const float* __restrict__ tc,
    const float* __restrict__ td,
    const float* __restrict__ mfmix,
    const float* __restrict__ tnw,
    const float* __restrict__ conseq,
    const int*   __restrict__ ridx,
    float* __restrict__ out0,   // [B]
    float* __restrict__ outN,   // [B,128]
    float* __restrict__ outM,   // [B,14]
    int B)
{
    const int tid    = blockIdx.x * blockDim.x + threadIdx.x;
    const int warp   = tid >> 5;
    const int lane   = tid & 31;
    const int nwarps = (gridDim.x * blockDim.x) >> 5;

    // ---- per-lane rules: r = lane + 32*k (k=0..3) ----
    float cq[4][8];
    int   mask[4];
#pragma unroll
    for (int k = 0; k < 4; ++k) {
        const int r = lane + 32 * k;
        const float4* cp = reinterpret_cast<const float4*>(conseq + r * 8);
        float4 c0 = cp[0], c1 = cp[1];
        cq[k][0] = c0.x; cq[k][1] = c0.y; cq[k][2] = c0.z; cq[k][3] = c0.w;
        cq[k][4] = c1.x; cq[k][5] = c1.y; cq[k][6] = c1.z; cq[k][7] = c1.w;
        int m = 0;
#pragma unroll
        for (int f = 0; f < 7; ++f) m |= (ridx[r * 7 + f] & 1) << f;
        mask[k] = m;
    }

    // Structure check: the 4 masks of a lane must agree on features 2..6.
    const int diff = (mask[0]^mask[1]) | (mask[0]^mask[2]) | (mask[0]^mask[3]);
    const bool fast = __all_sync(FULL_MASK, (diff & 0x7C) == 0);

    // Shuffle source lanes for the 5 shared features (mem index = 2f + set)
    const int src2 = 4  + ((mask[0] >> 2) & 1);
    const int src3 = 6  + ((mask[0] >> 3) & 1);
    const int src4 = 8  + ((mask[0] >> 4) & 1);
    const int src5 = 10 + ((mask[0] >> 5) & 1);
    const int src6 = 12 + ((mask[0] >> 6) & 1);

    const float alpha = 1.f / (1.f + __expf(-mfmix[0]));
    const float w     = 1.f / (1.f + __expf(-tnw[0]));

    // ---- element-invariant membership params (lanes 0..13: f=lane>>1, set=lane&1) ----
    const int j = (lane < 14) ? lane : 0;
    float muv, i2s, av, bv, cv, dv, iba, idc;
    {
        muv = mu[j];
        float s = fmaxf(sg[j], 1e-6f);
        i2s = 1.f / (2.f * s * s);
        float p0 = ta[j], p1 = tb[j], p2 = tc[j], p3 = td[j];
        float t;
        t = fminf(p0, p1); p1 = fmaxf(p0, p1); p0 = t;
        t = fminf(p2, p3); p3 = fmaxf(p2, p3); p2 = t;
        t = fminf(p0, p2); p2 = fmaxf(p0, p2); p0 = t;
        t = fminf(p1, p3); p3 = fmaxf(p1, p3); p1 = t;
        t = fminf(p1, p2); p2 = fmaxf(p1, p2); p1 = t;
        av = p0; bv = p1; cv = p2; dv = p3;
        iba = 1.f / (p1 - p0 + 1e-6f);
        idc = 1.f / (p3 - p2 + 1e-6f);
    }

    if (fast) {
        for (int b = warp; b < B; b += nwarps) {
            const float* xb = x + b * 7;           // 32-bit offset math
            float xv0 = __ldg(xb+0), xv1 = __ldg(xb+1), xv2 = __ldg(xb+2),
                  xv3 = __ldg(xb+3), xv4 = __ldg(xb+4), xv5 = __ldg(xb+5),
                  xv6 = __ldg(xb+6);

            // ---- membership (lanes 0..13) ----
            float memv = 0.f;
            if (lane < 14) {
                float xf = __ldg(xb + (lane >> 1));
                float t     = xf - muv;
                float gauss = __expf(-t * t * i2s);
                float left  = fminf(fmaxf((xf - av) * iba, 0.f), 1.f);
                float right = fminf(fmaxf((dv - xf) * idc, 0.f), 1.f);
                float flat  = (xf >= bv && xf <= cv) ? 1.f : 0.f;
                float trap  = fmaxf(fminf(left, right), flat);
                memv = trap + alpha * (gauss - trap);
                outM[b * 14 + lane] = memv;
            }

            // ---- gather this lane's 5 shared-feature memberships directly ----
            float g2 = __shfl_sync(FULL_MASK, memv, src2);
            float g3 = __shfl_sync(FULL_MASK, memv, src3);
            float g4 = __shfl_sync(FULL_MASK, memv, src4);
            float g5 = __shfl_sync(FULL_MASK, memv, src5);
            float g6 = __shfl_sync(FULL_MASK, memv, src6);
            float mA0 = __shfl_sync(FULL_MASK, memv, 0);
            float mB0 = __shfl_sync(FULL_MASK, memv, 1);
            float mA1 = __shfl_sync(FULL_MASK, memv, 2);
            float mB1 = __shfl_sync(FULL_MASK, memv, 3);

            float pp = ((g2 * g3) * (g4 * g5)) * g6;
            float pm = fminf(fminf(fminf(g2, g3), fminf(g4, g5)), g6);

            // ---- firing + fir*ro for this lane's 4 rules ----
            float f0, f1, f2, f3;
            float s1 = 0.f, s2 = 0.f;
#pragma unroll
            for (int k = 0; k < 4; ++k) {
                const int m = mask[k];
                float u = (m & 1) ? mB0 : mA0;   // feature 0
                float v = (m & 2) ? mB1 : mA1;   // feature 1
                float p  = pp * (u * v);
                float mn = fminf(pm, fminf(u, v));
                float f  = mn + w * (p - mn);
                if (k == 0) f0 = f; else if (k == 1) f1 = f; else if (k == 2) f2 = f; else f3 = f;
                float ro = cq[k][0];
                ro = fmaf(cq[k][1], xv0, ro);
                ro = fmaf(cq[k][2], xv1, ro);
                ro = fmaf(cq[k][3], xv2, ro);
                ro = fmaf(cq[k][4], xv3, ro);
                ro = fmaf(cq[k][5], xv4, ro);
                ro = fmaf(cq[k][6], xv5, ro);
                ro = fmaf(cq[k][7], xv6, ro);
                s1 += f;
                s2 = fmaf(f, ro, s2);
            }

            // ---- interleaved dual butterfly reduction ----
#pragma unroll
            for (int off = 16; off > 0; off >>= 1) {
                s1 += __shfl_xor_sync(FULL_MASK, s1, off);
                s2 += __shfl_xor_sync(FULL_MASK, s2, off);
            }
            const float inv = __fdividef(1.f, s1 + 1e-8f);

            float* nb = outN + b * 128 + lane;
            nb[0]  = f0 * inv;
            nb[32] = f1 * inv;
            nb[64] = f2 * inv;
            nb[96] = f3 * inv;
            if (lane == 0) out0[b] = s2 * inv;
        }
    } else {
        // ---- generic fallback (structure assumption violated) ----
        for (int b = warp; b < B; b += nwarps) {
            const float* xb = x + b * 7;
            float xv0 = __ldg(xb+0), xv1 = __ldg(xb+1), xv2 = __ldg(xb+2),
                  xv3 = __ldg(xb+3), xv4 = __ldg(xb+4), xv5 = __ldg(xb+5),
                  xv6 = __ldg(xb+6);
            float memv = 0.f;
            if (lane < 14) {
                float xfv = __ldg(xb + (lane >> 1));
                float t     = xfv - muv;
                float gauss = __expf(-t * t * i2s);
                float left  = fminf(fmaxf((xfv - av) * iba, 0.f), 1.f);
                float right = fminf(fmaxf((dv - xfv) * idc, 0.f), 1.f);
                float flat  = (xfv >= bv && xfv <= cv) ? 1.f : 0.f;
                float trap  = fmaxf(fminf(left, right), flat);
                memv = trap + alpha * (gauss - trap);
                outM[b * 14 + lane] = memv;
            }
            float mA[7], mB[7];
#pragma unroll
            for (int f = 0; f < 7; ++f) {
                mA[f] = __shfl_sync(FULL_MASK, memv, 2 * f);
                mB[f] = __shfl_sync(FULL_MASK, memv, 2 * f + 1);
            }
            float fir[4], s1 = 0.f, s2 = 0.f;
#pragma unroll
            for (int k = 0; k < 4; ++k) {
                const int m = mask[k];
                float p = 1.f, mn = 2.f;
#pragma unroll
                for (int f = 0; f < 7; ++f) {
                    float g = (m & (1 << f)) ? mB[f] : mA[f];
                    p *= g; mn = fminf(mn, g);
                }
                float fk = mn + w * (p - mn);
                fir[k] = fk;
                float ro = cq[k][0];
                ro = fmaf(cq[k][1], xv0, ro);
                ro = fmaf(cq[k][2], xv1, ro);
                ro = fmaf(cq[k][3], xv2, ro);
                ro = fmaf(cq[k][4], xv3, ro);
                ro = fmaf(cq[k][5], xv4, ro);
                ro = fmaf(cq[k][6], xv5, ro);
                ro = fmaf(cq[k][7], xv6, ro);
                s1 += fk;
                s2 = fmaf(fk, ro, s2);
            }
#pragma unroll
            for (int off = 16; off > 0; off >>= 1) {
                s1 += __shfl_xor_sync(FULL_MASK, s1, off);
                s2 += __shfl_xor_sync(FULL_MASK, s2, off);
            }
            const float inv = __fdividef(1.f, s1 + 1e-8f);
            float* nb = outN + b * 128 + lane;
            nb[0]  = fir[0] * inv;
            nb[32] = fir[1] * inv;
            nb[64] = fir[2] * inv;
            nb[96] = fir[3] * inv;
            if (lane == 0) out0[b] = s2 * inv;
        }
    }
}

extern "C" void kernel_launch(void* const* d_in, const int* in_sizes, int n_in,
                              void* d_out, int out_size) {
    const float* x      = (const float*)d_in[0];
    const float* mu     = (const float*)d_in[1];
    const float* sg     = (const float*)d_in[2];
    const float* ta     = (const float*)d_in[3];
    const float* tb     = (const float*)d_in[4];
    const float* tc     = (const float*)d_in[5];
    const float* td     = (const float*)d_in[6];
    const float* mfmix  = (const float*)d_in[7];
    const float* tnw    = (const float*)d_in[8];
    const float* conseq = (const float*)d_in[9];
    const int*   ridx   = (const int*)d_in[10];

    const int B = in_sizes[0] / 7;

    float* o  = (float*)d_out;
    float* oN = o + B;                // norm_firing [B,128]
    float* oM = o + B + B * 128;      // mem [B,14]

    // Single wave: 148 SMs x 5 blocks/SM, 128 threads each (20 warps/SM)
    anfis_kernel<<<740, 128>>>(x, mu, sg, ta, tb, tc, td, mfmix, tnw,
                               conseq, ridx, o, oN, oM, B);
}

// round 7
// speedup vs baseline: 1.6620x; 1.0297x over previous
#include <cuda_runtime.h>
#include <cuda_bf16.h>

#define FULL_MASK 0xffffffffu

__global__ __launch_bounds__(128, 4) void anfis_kernel(
    const float* __restrict__ x,
    const float* __restrict__ mu,
    const float* __restrict__ sg,
    const float* __restrict__ ta,
    const float* __restrict__ tb,
    const float* __restrict__ tc,
    const float* __restrict__ td,
    const float* __restrict__ mfmix,
    const float* __restrict__ tnw,
    const float* __restrict__ conseq,
    const int*   __restrict__ ridx,
    float* __restrict__ out0,   // [B]
    float* __restrict__ outN,   // [B,128]
    float* __restrict__ outM,   // [B,14]
    int B)
{
    const int tid    = blockIdx.x * blockDim.x + threadIdx.x;
    const int warp   = tid >> 5;
    const int lane   = tid & 31;
    const int nwarps = (gridDim.x * blockDim.x) >> 5;

    // ---- per-lane rules: r = 4*lane + k (k=0..3) -> float4 norm_firing store ----
    float cq[4][8];
    int   mask[4];
#pragma unroll
    for (int k = 0; k < 4; ++k) {
        const int r = 4 * lane + k;
        const float4* cp = reinterpret_cast<const float4*>(conseq + r * 8);
        float4 c0 = cp[0], c1 = cp[1];
        cq[k][0] = c0.x; cq[k][1] = c0.y; cq[k][2] = c0.z; cq[k][3] = c0.w;
        cq[k][4] = c1.x; cq[k][5] = c1.y; cq[k][6] = c1.z; cq[k][7] = c1.w;
        int m = 0;
#pragma unroll
        for (int f = 0; f < 7; ++f) m |= (ridx[r * 7 + f] & 1) << f;
        mask[k] = m;
    }

    // Structure check: the 4 masks of a lane must agree on features 0..4
    // (binary rule enumeration: k varies only features 5,6).
    const int diff = (mask[0]^mask[1]) | (mask[0]^mask[2]) | (mask[0]^mask[3]);
    const bool fast = __all_sync(FULL_MASK, (diff & 0x1F) == 0);

    // Gather source lanes for the 5 shared features (mem index = 2f + set)
    const int src0 = 0 + ((mask[0] >> 0) & 1);
    const int src1 = 2 + ((mask[0] >> 1) & 1);
    const int src2 = 4 + ((mask[0] >> 2) & 1);
    const int src3 = 6 + ((mask[0] >> 3) & 1);
    const int src4 = 8 + ((mask[0] >> 4) & 1);

    const float alpha = 1.f / (1.f + __expf(-mfmix[0]));
    const float w     = 1.f / (1.f + __expf(-tnw[0]));

    // ---- element-invariant membership params (lanes 0..27: j=lane%14) ----
    const int j = (lane < 14) ? lane : (lane < 28 ? lane - 14 : 0);
    float muv, i2s, av, bv, cv, dv, iba, idc;
    {
        muv = mu[j];
        float s = fmaxf(sg[j], 1e-6f);
        i2s = 1.f / (2.f * s * s);
        float p0 = ta[j], p1 = tb[j], p2 = tc[j], p3 = td[j];
        float t;
        t = fminf(p0, p1); p1 = fmaxf(p0, p1); p0 = t;
        t = fminf(p2, p3); p3 = fmaxf(p2, p3); p2 = t;
        t = fminf(p0, p2); p2 = fmaxf(p0, p2); p0 = t;
        t = fminf(p1, p3); p3 = fmaxf(p1, p3); p1 = t;
        t = fminf(p1, p2); p2 = fmaxf(p1, p2); p1 = t;
        av = p0; bv = p1; cv = p2; dv = p3;
        iba = 1.f / (p1 - p0 + 1e-6f);
        idc = 1.f / (p3 - p2 + 1e-6f);
    }

    if (fast) {
        for (int b0 = 2 * warp; b0 < B; b0 += 2 * nwarps) {
            const bool dual  = (b0 + 1 < B);
            const int active = dual ? 28 : 14;
            const float* xb  = x + b0 * 7;   // 14 contiguous floats span both rows

            // x broadcasts via uniform-address L1 loads (LSU pipe, independent)
            float ax0 = __ldg(xb+0),  ax1 = __ldg(xb+1),  ax2 = __ldg(xb+2),
                  ax3 = __ldg(xb+3),  ax4 = __ldg(xb+4),  ax5 = __ldg(xb+5),
                  ax6 = __ldg(xb+6);
            float bx0 = __ldg(xb+7),  bx1 = __ldg(xb+8),  bx2 = __ldg(xb+9),
                  bx3 = __ldg(xb+10), bx4 = __ldg(xb+11), bx5 = __ldg(xb+12),
                  bx6 = __ldg(xb+13);

            // ---- memberships for both elements across lanes 0..27 ----
            float memv = 0.f;
            if (lane < active) {
                float xf = __ldg(xb + (lane >> 1));  // lane = 14e + 2f + set
                float t     = xf - muv;
                float gauss = __expf(-t * t * i2s);
                float left  = fminf(fmaxf((xf - av) * iba, 0.f), 1.f);
                float right = fminf(fmaxf((dv - xf) * idc, 0.f), 1.f);
                float flat  = (xf >= bv && xf <= cv) ? 1.f : 0.f;
                float trap  = fmaxf(fminf(left, right), flat);
                memv = trap + alpha * (gauss - trap);
                outM[b0 * 14 + lane] = memv;
            }

            // ---- gathers: element A (lanes 0..13), element B (+14) ----
            float a_g0 = __shfl_sync(FULL_MASK, memv, src0);
            float b_g0 = __shfl_sync(FULL_MASK, memv, src0 + 14);
            float a_g1 = __shfl_sync(FULL_MASK, memv, src1);
            float b_g1 = __shfl_sync(FULL_MASK, memv, src1 + 14);
            float a_g2 = __shfl_sync(FULL_MASK, memv, src2);
            float b_g2 = __shfl_sync(FULL_MASK, memv, src2 + 14);
            float a_g3 = __shfl_sync(FULL_MASK, memv, src3);
            float b_g3 = __shfl_sync(FULL_MASK, memv, src3 + 14);
            float a_g4 = __shfl_sync(FULL_MASK, memv, src4);
            float b_g4 = __shfl_sync(FULL_MASK, memv, src4 + 14);
            // pair features 5 (lanes 10/11) and 6 (lanes 12/13)
            float aA5 = __shfl_sync(FULL_MASK, memv, 10);
            float aB5 = __shfl_sync(FULL_MASK, memv, 11);
            float aA6 = __shfl_sync(FULL_MASK, memv, 12);
            float aB6 = __shfl_sync(FULL_MASK, memv, 13);
            float bA5 = __shfl_sync(FULL_MASK, memv, 24);
            float bB5 = __shfl_sync(FULL_MASK, memv, 25);
            float bA6 = __shfl_sync(FULL_MASK, memv, 26);
            float bB6 = __shfl_sync(FULL_MASK, memv, 27);

            float a_pp = ((a_g0 * a_g1) * (a_g2 * a_g3)) * a_g4;
            float a_pm = fminf(fminf(fminf(a_g0, a_g1), fminf(a_g2, a_g3)), a_g4);
            float b_pp = ((b_g0 * b_g1) * (b_g2 * b_g3)) * b_g4;
            float b_pm = fminf(fminf(fminf(b_g0, b_g1), fminf(b_g2, b_g3)), b_g4);

            float firA[4], firB[4];
            float s1a = 0.f, s2a = 0.f, s1b = 0.f, s2b = 0.f;
#pragma unroll
            for (int k = 0; k < 4; ++k) {
                const int m = mask[k];
                // element A
                float u = (m & 32) ? aB5 : aA5;
                float v = (m & 64) ? aB6 : aA6;
                float p  = a_pp * (u * v);
                float mn = fminf(a_pm, fminf(u, v));
                float fA = mn + w * (p - mn);
                firA[k] = fA;
                // element B
                float u2 = (m & 32) ? bB5 : bA5;
                float v2 = (m & 64) ? bB6 : bA6;
                float p2  = b_pp * (u2 * v2);
                float mn2 = fminf(b_pm, fminf(u2, v2));
                float fB = mn2 + w * (p2 - mn2);
                firB[k] = fB;

                float roA = cq[k][0];
                roA = fmaf(cq[k][1], ax0, roA);
                roA = fmaf(cq[k][2], ax1, roA);
                roA = fmaf(cq[k][3], ax2, roA);
                roA = fmaf(cq[k][4], ax3, roA);
                roA = fmaf(cq[k][5], ax4, roA);
                roA = fmaf(cq[k][6], ax5, roA);
                roA = fmaf(cq[k][7], ax6, roA);
                float roB = cq[k][0];
                roB = fmaf(cq[k][1], bx0, roB);
                roB = fmaf(cq[k][2], bx1, roB);
                roB = fmaf(cq[k][3], bx2, roB);
                roB = fmaf(cq[k][4], bx3, roB);
                roB = fmaf(cq[k][5], bx4, roB);
                roB = fmaf(cq[k][6], bx5, roB);
                roB = fmaf(cq[k][7], bx6, roB);

                s1a += fA; s2a = fmaf(fA, roA, s2a);
                s1b += fB; s2b = fmaf(fB, roB, s2b);
            }

            // ---- 4 interleaved butterfly reduction chains ----
#pragma unroll
            for (int off = 16; off > 0; off >>= 1) {
                s1a += __shfl_xor_sync(FULL_MASK, s1a, off);
                s1b += __shfl_xor_sync(FULL_MASK, s1b, off);
                s2a += __shfl_xor_sync(FULL_MASK, s2a, off);
                s2b += __shfl_xor_sync(FULL_MASK, s2b, off);
            }
            const float invA = __fdividef(1.f, s1a + 1e-8f);
            const float invB = __fdividef(1.f, s1b + 1e-8f);

            float4 nfA = make_float4(firA[0]*invA, firA[1]*invA, firA[2]*invA, firA[3]*invA);
            reinterpret_cast<float4*>(outN + b0 * 128)[lane] = nfA;
            if (dual) {
                float4 nfB = make_float4(firB[0]*invB, firB[1]*invB, firB[2]*invB, firB[3]*invB);
                reinterpret_cast<float4*>(outN + (b0 + 1) * 128)[lane] = nfB;
            }
            if (lane == 0) {
                out0[b0] = s2a * invA;
                if (dual) out0[b0 + 1] = s2b * invB;
            }
        }
    } else {
        // ---- generic fallback (structure assumption violated): 1 element/iter ----
        for (int b = warp; b < B; b += nwarps) {
            const float* xb = x + b * 7;
            float xv0 = __ldg(xb+0), xv1 = __ldg(xb+1), xv2 = __ldg(xb+2),
                  xv3 = __ldg(xb+3), xv4 = __ldg(xb+4), xv5 = __ldg(xb+5),
                  xv6 = __ldg(xb+6);
            float memv = 0.f;
            if (lane < 14) {
                float xfv = __ldg(xb + (lane >> 1));
                float t     = xfv - muv;
                float gauss = __expf(-t * t * i2s);
                float left  = fminf(fmaxf((xfv - av) * iba, 0.f), 1.f);
                float right = fminf(fmaxf((dv - xfv) * idc, 0.f), 1.f);
                float flat  = (xfv >= bv && xfv <= cv) ? 1.f : 0.f;
                float trap  = fmaxf(fminf(left, right), flat);
                memv = trap + alpha * (gauss - trap);
                outM[b * 14 + lane] = memv;
            }
            float mA[7], mB[7];
#pragma unroll
            for (int f = 0; f < 7; ++f) {
                mA[f] = __shfl_sync(FULL_MASK, memv, 2 * f);
                mB[f] = __shfl_sync(FULL_MASK, memv, 2 * f + 1);
            }
            float fir[4], s1 = 0.f, s2 = 0.f;
#pragma unroll
            for (int k = 0; k < 4; ++k) {
                const int m = mask[k];
                float p = 1.f, mn = 2.f;
#pragma unroll
                for (int f = 0; f < 7; ++f) {
                    float g = (m & (1 << f)) ? mB[f] : mA[f];
                    p *= g; mn = fminf(mn, g);
                }
                float fk = mn + w * (p - mn);
                fir[k] = fk;
                float ro = cq[k][0];
                ro = fmaf(cq[k][1], xv0, ro);
                ro = fmaf(cq[k][2], xv1, ro);
                ro = fmaf(cq[k][3], xv2, ro);
                ro = fmaf(cq[k][4], xv3, ro);
                ro = fmaf(cq[k][5], xv4, ro);
                ro = fmaf(cq[k][6], xv5, ro);
                ro = fmaf(cq[k][7], xv6, ro);
                s1 += fk;
                s2 = fmaf(fk, ro, s2);
            }
#pragma unroll
            for (int off = 16; off > 0; off >>= 1) {
                s1 += __shfl_xor_sync(FULL_MASK, s1, off);
                s2 += __shfl_xor_sync(FULL_MASK, s2, off);
            }
            const float inv = __fdividef(1.f, s1 + 1e-8f);
            float4 nf = make_float4(fir[0]*inv, fir[1]*inv, fir[2]*inv, fir[3]*inv);
            reinterpret_cast<float4*>(outN + b * 128)[lane] = nf;
            if (lane == 0) out0[b] = s2 * inv;
        }
    }
}

extern "C" void kernel_launch(void* const* d_in, const int* in_sizes, int n_in,
                              void* d_out, int out_size) {
    const float* x      = (const float*)d_in[0];
    const float* mu     = (const float*)d_in[1];
    const float* sg     = (const float*)d_in[2];
    const float* ta     = (const float*)d_in[3];
    const float* tb     = (const float*)d_in[4];
    const float* tc     = (const float*)d_in[5];
    const float* td     = (const float*)d_in[6];
    const float* mfmix  = (const float*)d_in[7];
    const float* tnw    = (const float*)d_in[8];
    const float* conseq = (const float*)d_in[9];
    const int*   ridx   = (const int*)d_in[10];

    const int B = in_sizes[0] / 7;

    float* o  = (float*)d_out;
    float* oN = o + B;                // norm_firing [B,128]
    float* oM = o + B + B * 128;      // mem [B,14]

    // Single wave: 148 SMs x 4 blocks/SM, 128 threads (16 warps/SM), 2 elem/warp-iter
    anfis_kernel<<<592, 128>>>(x, mu, sg, ta, tb, tc, td, mfmix, tnw,
                               conseq, ridx, o, oN, oM, B);
}